// round 10
// baseline (speedup 1.0000x reference)
#include <cuda_runtime.h>
#include <cstdint>
#include <cstddef>

// ---------------- problem constants ----------------
#define MTOT 4096
#define NTOT 2048
#define K1   1024
#define K2   2048

#define BM 128
#define BN 128
#define BK 64
#define NS 3

#define KT1T (K1 / BK)           // 16
#define KTOT ((K1 + K2) / BK)    // 48

#define STAGE_A  (BM * BK * 4)               // 32768 B
#define STAGE_SZ (2 * STAGE_A)               // 65536 B (A then B)
#define SMEM_BYTES (NS * STAGE_SZ)           // 196608 B

// ---------------- scratch (__device__ globals: allocation-free) ----------------
__device__ float g_x [MTOT * (size_t)K1];
__device__ float g_h [MTOT * (size_t)K2];
__device__ float g_Wr[NTOT * (size_t)K1];
__device__ float g_Wz[NTOT * (size_t)K1];
__device__ float g_Wh[NTOT * (size_t)K1];
__device__ float g_Ur[NTOT * (size_t)K2];
__device__ float g_Uz[NTOT * (size_t)K2];
__device__ float g_Uh[NTOT * (size_t)K2];
__device__ float g_rh[MTOT * (size_t)NTOT];
__device__ float g_zb[MTOT * (size_t)NTOT];

// ---------------- helpers ----------------
__device__ __forceinline__ uint32_t smem_u32(const void* p) {
    uint32_t a;
    asm("{ .reg .u64 t; cvta.to.shared.u64 t, %1; cvt.u32.u64 %0, t; }" : "=r"(a) : "l"(p));
    return a;
}

__device__ __forceinline__ void cp16(uint32_t dst, const void* src) {
    asm volatile("cp.async.cg.shared.global [%0], [%1], 16;" :: "r"(dst), "l"(src));
}
__device__ __forceinline__ void cp_commit() {
    asm volatile("cp.async.commit_group;" ::: "memory");
}
__device__ __forceinline__ void cp_wait1() {
    asm volatile("cp.async.wait_group 1;" ::: "memory");
}

// ldmatrix x4 (b16): four 8x8 b16 matrices == four 8row x 4col fp32 tiles.
// Fragment map (thread t -> row t/4, col t%4) matches mma.tf32 A/B layouts.
__device__ __forceinline__ void ldm4(uint32_t* r, uint32_t addr) {
    asm volatile("ldmatrix.sync.aligned.m8n8.x4.shared.b16 {%0,%1,%2,%3}, [%4];"
                 : "=r"(r[0]), "=r"(r[1]), "=r"(r[2]), "=r"(r[3]) : "r"(addr));
}

__device__ __forceinline__ void mma_tf32(float* c, const uint32_t* a, uint32_t b0, uint32_t b1) {
    asm volatile(
        "mma.sync.aligned.m16n8k8.row.col.f32.tf32.tf32.f32 "
        "{%0,%1,%2,%3}, {%4,%5,%6,%7}, {%8,%9}, {%0,%1,%2,%3};"
        : "+f"(c[0]), "+f"(c[1]), "+f"(c[2]), "+f"(c[3])
        : "r"(a[0]), "r"(a[1]), "r"(a[2]), "r"(a[3]), "r"(b0), "r"(b1));
}

__device__ __forceinline__ float tf32r(float x) {
    float r;
    asm("cvt.rna.tf32.f32 %0, %1;" : "=f"(r) : "f"(x));
    return r;
}
__device__ __forceinline__ float sigf(float v) { return 1.f / (1.f + __expf(-v)); }
__device__ __forceinline__ float tanhfast(float v) { return 2.f / (1.f + __expf(-2.f * v)) - 1.f; }

// ---------------- tf32 rounding pre-pass (one launch, 8 segments) ----------------
struct RoundSegs {
    const float4* src[8];
    float4*       dst[8];
    int           n4[8];
};

__global__ void round_all(RoundSegs S) {
    const int s = blockIdx.y;
    const float4* __restrict__ in = S.src[s];
    float4* __restrict__ out = S.dst[s];
    const int n4 = S.n4[s];
    for (int i = blockIdx.x * blockDim.x + threadIdx.x; i < n4; i += gridDim.x * blockDim.x) {
        float4 v = in[i];
        v.x = tf32r(v.x); v.y = tf32r(v.y); v.z = tf32r(v.z); v.w = tf32r(v.w);
        out[i] = v;
    }
}

// ---------------- tile loader: compile-time leading dimension ----------------
// Each thread: 8 A rows (i*16 + tr) and 8 B rows, fixed 16B chunk c.
// SMEM layout: 256B rows, chunk c of row r at r*256 + ((c ^ (r&7))<<4).
template <int LD>
__device__ __forceinline__ void load_seg(const float* __restrict__ pa,
                                         const float* __restrict__ pb,
                                         uint32_t st, uint32_t soff) {
#pragma unroll
    for (int i = 0; i < 8; i++)
        cp16(st + soff + i * 4096u, pa + (size_t)i * 16 * LD);
#pragma unroll
    for (int i = 0; i < 8; i++)
        cp16(st + STAGE_A + soff + i * 4096u, pb + (size_t)i * 16 * LD);
}

// ---------------- fused dual-source GEMM ----------------
// acc[M,N] = A1@B1^T (K=1024) + A2@B2^T (K=2048), epilogue by EPI:
//  EPI 0 (r): out = tf32(sigmoid(acc+bias) * hprev)    -> g_rh
//  EPI 1 (z): out = sigmoid(acc+bias)                  -> g_zb
//  EPI 2 (h): out = z*tanh(acc+bias) + (1-z)*hprev     -> d_out
template <int EPI>
__global__ void __launch_bounds__(256, 2) gru_gemm(
    const float* __restrict__ A1, const float* __restrict__ B1,
    const float* __restrict__ A2, const float* __restrict__ B2,
    const float* __restrict__ bias, const float* __restrict__ hprev,
    const float* __restrict__ zbuf, float* __restrict__ out)
{
    extern __shared__ char smem[];
    const uint32_t sbase = smem_u32(smem);
    const int tid = threadIdx.x;
    const int wid = tid >> 5;
    const int lid = tid & 31;
    const int g   = lid >> 2;     // group id 0..7
    const int tq  = lid & 3;      // thread-in-group
    const int wm  = wid >> 1;     // 0..3 (M)
    const int wn  = wid & 1;      // 0..1 (N)
    const int tm  = blockIdx.x & 31;   // 32 M tiles
    const int tn  = blockIdx.x >> 5;   // 16 N tiles

    // -------- loader per-thread constants --------
    // idx = i*256 + tid  ->  row = i*16 + tr (tr = tid>>4), chunk c = tid&15.
    // (row & 7) == (tr & 7) for all i -> one swizzled chunk offset serves all rows.
    const int tr = tid >> 4;                 // 0..15
    const int c  = tid & 15;                 // 16B chunk (0..15)
    const uint32_t soff = (uint32_t)tr * 256u + (uint32_t)((c ^ (tr & 7)) << 4);

    const float* pa = A1 + (size_t)(tm * BM + tr) * K1 + c * 4;
    const float* pb = B1 + (size_t)(tn * BN + tr) * K1 + c * 4;

    // ldmatrix per-thread addressing (rows at 256B stride)
    const int lr = lid & 7;
    const int mi = lid >> 3;
    const int lo = mi & 1;        // +8 rows
    const int hi = mi >> 1;       // +1 chunk (k+4)

    uint32_t aoff[2]; int ars[2];
#pragma unroll
    for (int mt = 0; mt < 2; mt++) {
        const int r = wm * 32 + mt * 16 + lo * 8 + lr;
        aoff[mt] = (uint32_t)r * 256u;
        ars[mt] = r & 7;
    }
    uint32_t boff[4]; int brs[4];
#pragma unroll
    for (int j = 0; j < 4; j++) {
        const int r = wn * 64 + j * 16 + lo * 8 + lr;
        boff[j] = (uint32_t)r * 256u;
        brs[j] = r & 7;
    }

    float acc[2][8][4];
#pragma unroll
    for (int mt = 0; mt < 2; mt++)
#pragma unroll
        for (int nt = 0; nt < 8; nt++)
#pragma unroll
            for (int i = 0; i < 4; i++) acc[mt][nt][i] = 0.f;

    // -------- prologue: prefetch tiles 0,1 into stages 0,1 (both segment 1) --------
#pragma unroll
    for (int p = 0; p < 2; p++) {
        load_seg<K1>(pa, pb, sbase + p * STAGE_SZ, soff);
        pa += BK; pb += BK;
        cp_commit();
    }

    // -------- mainloop: one sync per tile, wait_group 1 --------
#pragma unroll 1
    for (int kt0 = 0; kt0 < KTOT; kt0 += NS) {
#pragma unroll
        for (int s = 0; s < NS; s++) {
            const int kt = kt0 + s;
            cp_wait1();          // tile kt's group complete
            __syncthreads();     // prior readers of the reload stage are done

            const int lt = kt + 2;
            if (lt < KTOT) {
                if (lt == KT1T) {   // switch to second K-source
                    pa = A2 + (size_t)(tm * BM + tr) * K2 + c * 4;
                    pb = B2 + (size_t)(tn * BN + tr) * K2 + c * 4;
                }
                const uint32_t st = sbase + ((s + 2) % NS) * STAGE_SZ;
                if (lt < KT1T) load_seg<K1>(pa, pb, st, soff);
                else           load_seg<K2>(pa, pb, st, soff);
                pa += BK; pb += BK;
            }
            cp_commit();         // unconditional: uniform group accounting

            const uint32_t sA = sbase + s * STAGE_SZ;
            const uint32_t sB = sA + STAGE_A;
#pragma unroll
            for (int q = 0; q < 8; q++) {
                const int ch = q * 2 + hi;    // 16B k-chunk this thread addresses (0..15)
                uint32_t a[2][4];
#pragma unroll
                for (int mt = 0; mt < 2; mt++)
                    ldm4(a[mt], sA + aoff[mt] + (uint32_t)((ch ^ ars[mt]) << 4));
                uint32_t bf[4][4];
#pragma unroll
                for (int j = 0; j < 4; j++)
                    ldm4(bf[j], sB + boff[j] + (uint32_t)((ch ^ brs[j]) << 4));
#pragma unroll
                for (int mt = 0; mt < 2; mt++)
#pragma unroll
                    for (int nt = 0; nt < 8; nt++)
                        mma_tf32(acc[mt][nt], a[mt], bf[nt >> 1][nt & 1], bf[nt >> 1][2 + (nt & 1)]);
            }
        }
    }

    // ---------------- epilogue ----------------
#pragma unroll
    for (int mt = 0; mt < 2; mt++) {
#pragma unroll
        for (int nt = 0; nt < 8; nt++) {
            const int n = tn * BN + wn * 64 + nt * 8 + tq * 2;
            const float2 bi = *(const float2*)(bias + n);
#pragma unroll
            for (int half = 0; half < 2; half++) {
                const int m = tm * BM + wm * 32 + mt * 16 + g + half * 8;
                const size_t idx = (size_t)m * NTOT + n;
                float v0 = acc[mt][nt][half * 2 + 0] + bi.x;
                float v1 = acc[mt][nt][half * 2 + 1] + bi.y;
                float2 o;
                if (EPI == 0) {
                    const float2 h = *(const float2*)(hprev + idx);
                    o.x = tf32r(sigf(v0) * h.x);
                    o.y = tf32r(sigf(v1) * h.y);
                } else if (EPI == 1) {
                    o.x = sigf(v0);
                    o.y = sigf(v1);
                } else {
                    const float2 h = *(const float2*)(hprev + idx);
                    const float2 z = *(const float2*)(zbuf + idx);
                    o.x = z.x * tanhfast(v0) + (1.f - z.x) * h.x;
                    o.y = z.y * tanhfast(v1) + (1.f - z.y) * h.y;
                }
                *(float2*)(out + idx) = o;
            }
        }
    }
}

// ---------------- host launcher ----------------
extern "C" void kernel_launch(void* const* d_in, const int* in_sizes, int n_in,
                              void* d_out, int out_size) {
    (void)in_sizes; (void)n_in; (void)out_size;
    // metadata order: x, hprev, Wh, Wz, Wr, Uh, Uz, Ur, bh, bz, br
    const float* x     = (const float*)d_in[0];
    const float* hprev = (const float*)d_in[1];
    const float* Wh    = (const float*)d_in[2];
    const float* Wz    = (const float*)d_in[3];
    const float* Wr    = (const float*)d_in[4];
    const float* Uh    = (const float*)d_in[5];
    const float* Uz    = (const float*)d_in[6];
    const float* Ur    = (const float*)d_in[7];
    const float* bh    = (const float*)d_in[8];
    const float* bz    = (const float*)d_in[9];
    const float* br    = (const float*)d_in[10];
    float* out = (float*)d_out;

    float *px, *ph, *pWr, *pWz, *pWh, *pUr, *pUz, *pUh, *prh, *pzb;
    cudaGetSymbolAddress((void**)&px,  g_x);
    cudaGetSymbolAddress((void**)&ph,  g_h);
    cudaGetSymbolAddress((void**)&pWr, g_Wr);
    cudaGetSymbolAddress((void**)&pWz, g_Wz);
    cudaGetSymbolAddress((void**)&pWh, g_Wh);
    cudaGetSymbolAddress((void**)&pUr, g_Ur);
    cudaGetSymbolAddress((void**)&pUz, g_Uz);
    cudaGetSymbolAddress((void**)&pUh, g_Uh);
    cudaGetSymbolAddress((void**)&prh, g_rh);
    cudaGetSymbolAddress((void**)&pzb, g_zb);

    cudaFuncSetAttribute(gru_gemm<0>, cudaFuncAttributeMaxDynamicSharedMemorySize, SMEM_BYTES);
    cudaFuncSetAttribute(gru_gemm<1>, cudaFuncAttributeMaxDynamicSharedMemorySize, SMEM_BYTES);
    cudaFuncSetAttribute(gru_gemm<2>, cudaFuncAttributeMaxDynamicSharedMemorySize, SMEM_BYTES);

    // tf32 pre-round all GEMM operands into scratch (one launch)
    RoundSegs S;
    S.src[0] = (const float4*)x;     S.dst[0] = (float4*)px;  S.n4[0] = MTOT * K1 / 4;
    S.src[1] = (const float4*)hprev; S.dst[1] = (float4*)ph;  S.n4[1] = MTOT * K2 / 4;
    S.src[2] = (const float4*)Wr;    S.dst[2] = (float4*)pWr; S.n4[2] = NTOT * K1 / 4;
    S.src[3] = (const float4*)Wz;    S.dst[3] = (float4*)pWz; S.n4[3] = NTOT * K1 / 4;
    S.src[4] = (const float4*)Wh;    S.dst[4] = (float4*)pWh; S.n4[4] = NTOT * K1 / 4;
    S.src[5] = (const float4*)Ur;    S.dst[5] = (float4*)pUr; S.n4[5] = NTOT * K2 / 4;
    S.src[6] = (const float4*)Uz;    S.dst[6] = (float4*)pUz; S.n4[6] = NTOT * K2 / 4;
    S.src[7] = (const float4*)Uh;    S.dst[7] = (float4*)pUh; S.n4[7] = NTOT * K2 / 4;
    round_all<<<dim3(256, 8), 256>>>(S);

    const dim3 grid(512), block(256);
    // r-gate: g_rh = tf32(sigmoid(x@Wr^T + h@Ur^T + br) * hprev)
    gru_gemm<0><<<grid, block, SMEM_BYTES>>>(px, pWr, ph, pUr, br, hprev, nullptr, prh);
    // z-gate: g_zb = sigmoid(x@Wz^T + h@Uz^T + bz)
    gru_gemm<1><<<grid, block, SMEM_BYTES>>>(px, pWz, ph, pUz, bz, nullptr, nullptr, pzb);
    // h-gate: out = z * tanh(x@Wh^T + rh@Uh^T + bh) + (1-z) * hprev
    gru_gemm<2><<<grid, block, SMEM_BYTES>>>(px, pWh, prh, pUh, bh, hprev, pzb, out);
}

// round 11
// speedup vs baseline: 1.1872x; 1.1872x over previous
#include <cuda_runtime.h>
#include <cstdint>
#include <cstddef>

// ---------------- problem constants ----------------
#define MTOT 4096
#define NTOT 2048
#define K1   1024
#define K2   2048

#define BM 64
#define BN 128
#define BK 32
#define NS 3

#define KT1  (K1 / BK)           // 32
#define KTOT ((K1 + K2) / BK)    // 96

#define STAGE_A  (BM * BK * 4)               // 8192 B
#define STAGE_B  (BN * BK * 4)               // 16384 B
#define STAGE_SZ (STAGE_A + STAGE_B)         // 24576 B
#define SMEM_BYTES (NS * STAGE_SZ)           // 73728 B -> 3 CTAs/SM

// ---------------- scratch (__device__ globals: allocation-free) ----------------
__device__ float g_x [MTOT * (size_t)K1];
__device__ float g_h [MTOT * (size_t)K2];
__device__ float g_Wr[NTOT * (size_t)K1];
__device__ float g_Wz[NTOT * (size_t)K1];
__device__ float g_Wh[NTOT * (size_t)K1];
__device__ float g_Ur[NTOT * (size_t)K2];
__device__ float g_Uz[NTOT * (size_t)K2];
__device__ float g_Uh[NTOT * (size_t)K2];
__device__ float g_rh[MTOT * (size_t)NTOT];
__device__ float g_zb[MTOT * (size_t)NTOT];

// ---------------- helpers ----------------
__device__ __forceinline__ uint32_t smem_u32(const void* p) {
    uint32_t a;
    asm("{ .reg .u64 t; cvta.to.shared.u64 t, %1; cvt.u32.u64 %0, t; }" : "=r"(a) : "l"(p));
    return a;
}

__device__ __forceinline__ void cp16(uint32_t dst, const void* src) {
    asm volatile("cp.async.cg.shared.global [%0], [%1], 16;" :: "r"(dst), "l"(src));
}
__device__ __forceinline__ void cp_commit() {
    asm volatile("cp.async.commit_group;" ::: "memory");
}
__device__ __forceinline__ void cp_wait1() {
    asm volatile("cp.async.wait_group 1;" ::: "memory");
}

// ldmatrix x4 (b16): four 8x8 b16 matrices == four 8row x 4col fp32 tiles.
// Fragment map (thread t -> row t/4, col t%4) matches mma.tf32 A/B layouts.
__device__ __forceinline__ void ldm4(uint32_t* r, uint32_t addr) {
    asm volatile("ldmatrix.sync.aligned.m8n8.x4.shared.b16 {%0,%1,%2,%3}, [%4];"
                 : "=r"(r[0]), "=r"(r[1]), "=r"(r[2]), "=r"(r[3]) : "r"(addr));
}

__device__ __forceinline__ void mma_tf32(float* c, const uint32_t* a, uint32_t b0, uint32_t b1) {
    asm volatile(
        "mma.sync.aligned.m16n8k8.row.col.f32.tf32.tf32.f32 "
        "{%0,%1,%2,%3}, {%4,%5,%6,%7}, {%8,%9}, {%0,%1,%2,%3};"
        : "+f"(c[0]), "+f"(c[1]), "+f"(c[2]), "+f"(c[3])
        : "r"(a[0]), "r"(a[1]), "r"(a[2]), "r"(a[3]), "r"(b0), "r"(b1));
}

__device__ __forceinline__ float tf32r(float x) {
    float r;
    asm("cvt.rna.tf32.f32 %0, %1;" : "=f"(r) : "f"(x));
    return r;
}
__device__ __forceinline__ float sigf(float v) { return 1.f / (1.f + __expf(-v)); }
__device__ __forceinline__ float tanhfast(float v) { return 2.f / (1.f + __expf(-2.f * v)) - 1.f; }

// ---------------- tf32 rounding pre-pass (one launch, 8 segments) ----------------
struct RoundSegs {
    const float4* src[8];
    float4*       dst[8];
    int           n4[8];
};

__global__ void round_all(RoundSegs S) {
    const int s = blockIdx.y;
    const float4* __restrict__ in = S.src[s];
    float4* __restrict__ out = S.dst[s];
    const int n4 = S.n4[s];
    for (int i = blockIdx.x * blockDim.x + threadIdx.x; i < n4; i += gridDim.x * blockDim.x) {
        float4 v = in[i];
        v.x = tf32r(v.x); v.y = tf32r(v.y); v.z = tf32r(v.z); v.w = tf32r(v.w);
        out[i] = v;
    }
}

// ---------------- tile loader (compile-time leading dimension) ----------------
// Per thread: 2 A rows (i*32 + tr, i<2) and 4 B rows (i*32 + tr, i<4), chunk c.
// (row & 7) == (tr & 7) -> one swizzled chunk offset serves all rows.
template <int LD>
__device__ __forceinline__ void load_seg(const float* __restrict__ pa,
                                         const float* __restrict__ pb,
                                         uint32_t st, uint32_t soff) {
#pragma unroll
    for (int i = 0; i < 2; i++)
        cp16(st + soff + i * 4096u, pa + (size_t)i * 32 * LD);
#pragma unroll
    for (int i = 0; i < 4; i++)
        cp16(st + STAGE_A + soff + i * 4096u, pb + (size_t)i * 32 * LD);
}

// ---------------- fused dual-source GEMM ----------------
// acc[M,N] = A1@B1^T (K=1024) + A2@B2^T (K=2048), epilogue by EPI:
//  EPI 0 (r): out = tf32(sigmoid(acc+bias) * hprev)    -> g_rh
//  EPI 1 (z): out = sigmoid(acc+bias)                  -> g_zb
//  EPI 2 (h): out = z*tanh(acc+bias) + (1-z)*hprev     -> d_out
template <int EPI>
__global__ void __launch_bounds__(256, 3) gru_gemm(
    const float* __restrict__ A1, const float* __restrict__ B1,
    const float* __restrict__ A2, const float* __restrict__ B2,
    const float* __restrict__ bias, const float* __restrict__ hprev,
    const float* __restrict__ zbuf, float* __restrict__ out)
{
    extern __shared__ char smem[];
    const uint32_t sbase = smem_u32(smem);
    const int tid = threadIdx.x;
    const int wid = tid >> 5;
    const int lid = tid & 31;
    const int g   = lid >> 2;     // group id 0..7
    const int tq  = lid & 3;      // thread-in-group
    const int wm  = wid >> 2;     // 0..1 (M), 32 rows each
    const int wn  = wid & 3;      // 0..3 (N), 32 cols each
    const int tm  = blockIdx.x & 63;   // 64 M tiles (fast dim -> B-tile sharing in L2)
    const int tn  = blockIdx.x >> 6;   // 16 N tiles

    // -------- loader per-thread constants --------
    const int tr = tid >> 3;                 // 0..31
    const int c  = tid & 7;                  // 16B chunk
    const uint32_t soff = (uint32_t)tr * 128u + (uint32_t)((c ^ (tr & 7)) << 4);

    const float* pa = A1 + (size_t)(tm * BM + tr) * K1 + c * 4;
    const float* pb = B1 + (size_t)(tn * BN + tr) * K1 + c * 4;

    // ldmatrix per-thread addressing
    const int lr = lid & 7;
    const int mi = lid >> 3;
    const int lo = mi & 1;        // +8 rows
    const int hi = mi >> 1;       // +1 chunk (k+4)

    uint32_t aoff[2]; int ars[2];
#pragma unroll
    for (int mt = 0; mt < 2; mt++) {
        const int r = wm * 32 + mt * 16 + lo * 8 + lr;
        aoff[mt] = (uint32_t)r * 128u;
        ars[mt] = r & 7;
    }
    uint32_t boff[2]; int brs[2];
#pragma unroll
    for (int j = 0; j < 2; j++) {
        const int r = wn * 32 + j * 16 + lo * 8 + lr;
        boff[j] = (uint32_t)r * 128u;
        brs[j] = r & 7;
    }

    float acc[2][4][4];
#pragma unroll
    for (int mt = 0; mt < 2; mt++)
#pragma unroll
        for (int nt = 0; nt < 4; nt++)
#pragma unroll
            for (int i = 0; i < 4; i++) acc[mt][nt][i] = 0.f;

    // -------- prologue: prefetch tiles 0,1 into stages 0,1 --------
#pragma unroll
    for (int p = 0; p < 2; p++) {
        load_seg<K1>(pa, pb, sbase + p * STAGE_SZ, soff);
        pa += BK; pb += BK;
        cp_commit();
    }

    // -------- mainloop: one sync per tile, wait_group 1 --------
#pragma unroll 1
    for (int kt0 = 0; kt0 < KTOT; kt0 += NS) {
#pragma unroll
        for (int s = 0; s < NS; s++) {
            const int kt = kt0 + s;
            cp_wait1();          // tile kt's group complete
            __syncthreads();     // prior readers of the reload stage are done

            const int lt = kt + 2;
            if (lt < KTOT) {
                if (lt == KT1) {   // switch to second K-source
                    pa = A2 + (size_t)(tm * BM + tr) * K2 + c * 4;
                    pb = B2 + (size_t)(tn * BN + tr) * K2 + c * 4;
                }
                const uint32_t st = sbase + ((s + 2) % NS) * STAGE_SZ;
                if (lt < KT1) load_seg<K1>(pa, pb, st, soff);
                else          load_seg<K2>(pa, pb, st, soff);
                pa += BK; pb += BK;
            }
            cp_commit();         // unconditional: uniform group accounting

            const uint32_t sA = sbase + s * STAGE_SZ;
            const uint32_t sB = sA + STAGE_A;
#pragma unroll
            for (int q = 0; q < 4; q++) {
                const int ch = q * 2 + hi;    // 16B k-chunk this thread addresses
                uint32_t a[2][4];
#pragma unroll
                for (int mt = 0; mt < 2; mt++)
                    ldm4(a[mt], sA + aoff[mt] + (uint32_t)((ch ^ ars[mt]) << 4));
                uint32_t bf[2][4];
#pragma unroll
                for (int j = 0; j < 2; j++)
                    ldm4(bf[j], sB + boff[j] + (uint32_t)((ch ^ brs[j]) << 4));
#pragma unroll
                for (int mt = 0; mt < 2; mt++)
#pragma unroll
                    for (int nt = 0; nt < 4; nt++)
                        mma_tf32(acc[mt][nt], a[mt], bf[nt >> 1][nt & 1], bf[nt >> 1][2 + (nt & 1)]);
            }
        }
    }

    // ---------------- epilogue ----------------
#pragma unroll
    for (int mt = 0; mt < 2; mt++) {
#pragma unroll
        for (int nt = 0; nt < 4; nt++) {
            const int n = tn * BN + wn * 32 + nt * 8 + tq * 2;
            const float2 bi = *(const float2*)(bias + n);
#pragma unroll
            for (int half = 0; half < 2; half++) {
                const int m = tm * BM + wm * 32 + mt * 16 + g + half * 8;
                const size_t idx = (size_t)m * NTOT + n;
                float v0 = acc[mt][nt][half * 2 + 0] + bi.x;
                float v1 = acc[mt][nt][half * 2 + 1] + bi.y;
                float2 o;
                if (EPI == 0) {
                    const float2 h = *(const float2*)(hprev + idx);
                    o.x = tf32r(sigf(v0) * h.x);
                    o.y = tf32r(sigf(v1) * h.y);
                } else if (EPI == 1) {
                    o.x = sigf(v0);
                    o.y = sigf(v1);
                } else {
                    const float2 h = *(const float2*)(hprev + idx);
                    const float2 z = *(const float2*)(zbuf + idx);
                    o.x = z.x * tanhfast(v0) + (1.f - z.x) * h.x;
                    o.y = z.y * tanhfast(v1) + (1.f - z.y) * h.y;
                }
                *(float2*)(out + idx) = o;
            }
        }
    }
}

// ---------------- host launcher ----------------
extern "C" void kernel_launch(void* const* d_in, const int* in_sizes, int n_in,
                              void* d_out, int out_size) {
    (void)in_sizes; (void)n_in; (void)out_size;
    // metadata order: x, hprev, Wh, Wz, Wr, Uh, Uz, Ur, bh, bz, br
    const float* x     = (const float*)d_in[0];
    const float* hprev = (const float*)d_in[1];
    const float* Wh    = (const float*)d_in[2];
    const float* Wz    = (const float*)d_in[3];
    const float* Wr    = (const float*)d_in[4];
    const float* Uh    = (const float*)d_in[5];
    const float* Uz    = (const float*)d_in[6];
    const float* Ur    = (const float*)d_in[7];
    const float* bh    = (const float*)d_in[8];
    const float* bz    = (const float*)d_in[9];
    const float* br    = (const float*)d_in[10];
    float* out = (float*)d_out;

    float *px, *ph, *pWr, *pWz, *pWh, *pUr, *pUz, *pUh, *prh, *pzb;
    cudaGetSymbolAddress((void**)&px,  g_x);
    cudaGetSymbolAddress((void**)&ph,  g_h);
    cudaGetSymbolAddress((void**)&pWr, g_Wr);
    cudaGetSymbolAddress((void**)&pWz, g_Wz);
    cudaGetSymbolAddress((void**)&pWh, g_Wh);
    cudaGetSymbolAddress((void**)&pUr, g_Ur);
    cudaGetSymbolAddress((void**)&pUz, g_Uz);
    cudaGetSymbolAddress((void**)&pUh, g_Uh);
    cudaGetSymbolAddress((void**)&prh, g_rh);
    cudaGetSymbolAddress((void**)&pzb, g_zb);

    cudaFuncSetAttribute(gru_gemm<0>, cudaFuncAttributeMaxDynamicSharedMemorySize, SMEM_BYTES);
    cudaFuncSetAttribute(gru_gemm<1>, cudaFuncAttributeMaxDynamicSharedMemorySize, SMEM_BYTES);
    cudaFuncSetAttribute(gru_gemm<2>, cudaFuncAttributeMaxDynamicSharedMemorySize, SMEM_BYTES);

    // tf32 pre-round all GEMM operands into scratch (one launch)
    RoundSegs S;
    S.src[0] = (const float4*)x;     S.dst[0] = (float4*)px;  S.n4[0] = MTOT * K1 / 4;
    S.src[1] = (const float4*)hprev; S.dst[1] = (float4*)ph;  S.n4[1] = MTOT * K2 / 4;
    S.src[2] = (const float4*)Wr;    S.dst[2] = (float4*)pWr; S.n4[2] = NTOT * K1 / 4;
    S.src[3] = (const float4*)Wz;    S.dst[3] = (float4*)pWz; S.n4[3] = NTOT * K1 / 4;
    S.src[4] = (const float4*)Wh;    S.dst[4] = (float4*)pWh; S.n4[4] = NTOT * K1 / 4;
    S.src[5] = (const float4*)Ur;    S.dst[5] = (float4*)pUr; S.n4[5] = NTOT * K2 / 4;
    S.src[6] = (const float4*)Uz;    S.dst[6] = (float4*)pUz; S.n4[6] = NTOT * K2 / 4;
    S.src[7] = (const float4*)Uh;    S.dst[7] = (float4*)pUh; S.n4[7] = NTOT * K2 / 4;
    round_all<<<dim3(256, 8), 256>>>(S);

    const dim3 grid(1024), block(256);
    // r-gate: g_rh = tf32(sigmoid(x@Wr^T + h@Ur^T + br) * hprev)
    gru_gemm<0><<<grid, block, SMEM_BYTES>>>(px, pWr, ph, pUr, br, hprev, nullptr, prh);
    // z-gate: g_zb = sigmoid(x@Wz^T + h@Uz^T + bz)
    gru_gemm<1><<<grid, block, SMEM_BYTES>>>(px, pWz, ph, pUz, bz, nullptr, nullptr, pzb);
    // h-gate: out = z * tanh(x@Wh^T + rh@Uh^T + bh) + (1-z) * hprev
    gru_gemm<2><<<grid, block, SMEM_BYTES>>>(px, pWh, prh, pUh, bh, hprev, pzb, out);
}

// round 12
// speedup vs baseline: 1.2179x; 1.0258x over previous
#include <cuda_runtime.h>
#include <cstdint>
#include <cstddef>

// ---------------- problem constants ----------------
#define MTOT 4096
#define NTOT 2048
#define K1   1024
#define K2   2048

#define BM 64
#define BN 128
#define BK 32
#define NS 3

#define KT1  (K1 / BK)           // 32
#define KTOT ((K1 + K2) / BK)    // 96

#define STAGE_A  (BM * BK * 4)               // 8192 B
#define STAGE_B  (BN * BK * 4)               // 16384 B
#define STAGE_SZ (STAGE_A + STAGE_B)         // 24576 B
#define SMEM_BYTES (NS * STAGE_SZ)           // 73728 B -> 3 CTAs/SM

// ---------------- scratch (__device__ globals: allocation-free) ----------------
__device__ float g_x [MTOT * (size_t)K1];
__device__ float g_h [MTOT * (size_t)K2];
__device__ float g_Wr[NTOT * (size_t)K1];
__device__ float g_Wz[NTOT * (size_t)K1];
__device__ float g_Wh[NTOT * (size_t)K1];
__device__ float g_Ur[NTOT * (size_t)K2];
__device__ float g_Uz[NTOT * (size_t)K2];
__device__ float g_Uh[NTOT * (size_t)K2];
__device__ float g_rh[MTOT * (size_t)NTOT];
__device__ float g_zb[MTOT * (size_t)NTOT];

// ---------------- helpers ----------------
__device__ __forceinline__ uint32_t smem_u32(const void* p) {
    uint32_t a;
    asm("{ .reg .u64 t; cvta.to.shared.u64 t, %1; cvt.u32.u64 %0, t; }" : "=r"(a) : "l"(p));
    return a;
}

__device__ __forceinline__ void cp16(uint32_t dst, const void* src) {
    asm volatile("cp.async.cg.shared.global [%0], [%1], 16;" :: "r"(dst), "l"(src));
}
__device__ __forceinline__ void cp_commit() {
    asm volatile("cp.async.commit_group;" ::: "memory");
}
__device__ __forceinline__ void cp_wait1() {
    asm volatile("cp.async.wait_group 1;" ::: "memory");
}

// ldmatrix x4 (b16): four 8x8 b16 matrices == four 8row x 4col fp32 tiles.
__device__ __forceinline__ void ldm4(uint32_t* r, uint32_t addr) {
    asm volatile("ldmatrix.sync.aligned.m8n8.x4.shared.b16 {%0,%1,%2,%3}, [%4];"
                 : "=r"(r[0]), "=r"(r[1]), "=r"(r[2]), "=r"(r[3]) : "r"(addr));
}

__device__ __forceinline__ void mma_tf32(float* c, const uint32_t* a, uint32_t b0, uint32_t b1) {
    asm volatile(
        "mma.sync.aligned.m16n8k8.row.col.f32.tf32.tf32.f32 "
        "{%0,%1,%2,%3}, {%4,%5,%6,%7}, {%8,%9}, {%0,%1,%2,%3};"
        : "+f"(c[0]), "+f"(c[1]), "+f"(c[2]), "+f"(c[3])
        : "r"(a[0]), "r"(a[1]), "r"(a[2]), "r"(a[3]), "r"(b0), "r"(b1));
}

__device__ __forceinline__ float tf32r(float x) {
    float r;
    asm("cvt.rna.tf32.f32 %0, %1;" : "=f"(r) : "f"(x));
    return r;
}
__device__ __forceinline__ float sigf(float v) { return 1.f / (1.f + __expf(-v)); }
__device__ __forceinline__ float tanhfast(float v) { return 2.f / (1.f + __expf(-2.f * v)) - 1.f; }

// ---------------- tf32 rounding pre-pass (one launch, 8 segments) ----------------
struct RoundSegs {
    const float4* src[8];
    float4*       dst[8];
    int           n4[8];
};

__global__ void round_all(RoundSegs S) {
    const int s = blockIdx.y;
    const float4* __restrict__ in = S.src[s];
    float4* __restrict__ out = S.dst[s];
    const int n4 = S.n4[s];
    for (int i = blockIdx.x * blockDim.x + threadIdx.x; i < n4; i += gridDim.x * blockDim.x) {
        float4 v = in[i];
        v.x = tf32r(v.x); v.y = tf32r(v.y); v.z = tf32r(v.z); v.w = tf32r(v.w);
        out[i] = v;
    }
}

// ---------------- tile loader (compile-time leading dimension) ----------------
template <int LD>
__device__ __forceinline__ void load_seg(const float* __restrict__ pa,
                                         const float* __restrict__ pb,
                                         uint32_t st, uint32_t soff) {
#pragma unroll
    for (int i = 0; i < 2; i++)
        cp16(st + soff + i * 4096u, pa + (size_t)i * 32 * LD);
#pragma unroll
    for (int i = 0; i < 4; i++)
        cp16(st + STAGE_A + soff + i * 4096u, pb + (size_t)i * 32 * LD);
}

// ---------------- fused dual-source GEMM ----------------
// MODE 0 (fused r+z): grid 2048; N-half selects gate:
//   r: outr = tf32(sigmoid(acc+br) * hprev)   z: outz = sigmoid(acc+bz)
// MODE 1 (h): grid 1024; out = z*tanh(acc+bh) + (1-z)*hprev
template <int MODE>
__global__ void __launch_bounds__(256, 3) gru_gemm(
    const float* __restrict__ A1, const float* __restrict__ A2,
    const float* __restrict__ B1r, const float* __restrict__ B2r,
    const float* __restrict__ B1z, const float* __restrict__ B2z,
    const float* __restrict__ biasr, const float* __restrict__ biasz,
    const float* __restrict__ hprev, const float* __restrict__ zbuf,
    float* __restrict__ outr, float* __restrict__ outz)
{
    extern __shared__ char smem[];
    const uint32_t sbase = smem_u32(smem);
    const int tid = threadIdx.x;
    const int wid = tid >> 5;
    const int lid = tid & 31;
    const int g   = lid >> 2;     // group id 0..7
    const int tq  = lid & 3;      // thread-in-group
    const int wm  = wid >> 2;     // 0..1 (M)
    const int wn  = wid & 3;      // 0..3 (N)
    const int bx  = blockIdx.x;
    const int tm  = bx & 63;      // fast dim -> B-tile sharing in L2

    int tn;
    bool zg = false;
    const float* B1; const float* B2; const float* bias; float* out;
    if (MODE == 0) {
        const int tnn = bx >> 6;              // 0..31
        zg = tnn >= 16;
        tn = tnn & 15;
        B1 = zg ? B1z : B1r;  B2 = zg ? B2z : B2r;
        bias = zg ? biasz : biasr;
        out  = zg ? outz : outr;
    } else {
        tn = bx >> 6;                         // 0..15
        B1 = B1r; B2 = B2r; bias = biasr; out = outr;
    }

    // -------- loader per-thread constants --------
    const int tr = tid >> 3;                 // 0..31
    const int c  = tid & 7;                  // 16B chunk
    const uint32_t soff = (uint32_t)tr * 128u + (uint32_t)((c ^ (tr & 7)) << 4);

    const float* pa = A1 + (size_t)(tm * BM + tr) * K1 + c * 4;
    const float* pb = B1 + (size_t)(tn * BN + tr) * K1 + c * 4;

    // -------- ldmatrix addressing (lean) --------
    // fragment row = {wm|wn}*32 + {mt|j}*16 + lo*8 + lr; row&7 == lr for ALL
    // fragments, so one swizzled chunk term oq[q] serves every ldm4.
    const int lr = lid & 7;
    const int mi = lid >> 3;
    const int lo = mi & 1;        // +8 rows
    const int hi = mi >> 1;       // +1 chunk (k+4)

    const uint32_t baseA = sbase + (uint32_t)(wm * 4096 + lo * 1024 + lr * 128);
    const uint32_t baseB = sbase + STAGE_A + (uint32_t)(wn * 4096 + lo * 1024 + lr * 128);
    uint32_t oq[4];
#pragma unroll
    for (int q = 0; q < 4; q++)
        oq[q] = (uint32_t)(((2 * q + hi) ^ lr) << 4);

    float acc[2][4][4];
#pragma unroll
    for (int mt = 0; mt < 2; mt++)
#pragma unroll
        for (int nt = 0; nt < 4; nt++)
#pragma unroll
            for (int i = 0; i < 4; i++) acc[mt][nt][i] = 0.f;

    // -------- prologue: prefetch tiles 0,1 into stages 0,1 --------
#pragma unroll
    for (int p = 0; p < 2; p++) {
        load_seg<K1>(pa, pb, sbase + p * STAGE_SZ, soff);
        pa += BK; pb += BK;
        cp_commit();
    }

    // -------- mainloop: one sync per tile, wait_group 1 --------
#pragma unroll 1
    for (int kt0 = 0; kt0 < KTOT; kt0 += NS) {
#pragma unroll
        for (int s = 0; s < NS; s++) {
            const int kt = kt0 + s;
            cp_wait1();          // tile kt's group complete
            __syncthreads();     // prior readers of the reload stage are done

            const int lt = kt + 2;
            if (lt < KTOT) {
                if (lt == KT1) {   // switch to second K-source
                    pa = A2 + (size_t)(tm * BM + tr) * K2 + c * 4;
                    pb = B2 + (size_t)(tn * BN + tr) * K2 + c * 4;
                }
                const uint32_t st = sbase + ((s + 2) % NS) * STAGE_SZ;
                if (lt < KT1) load_seg<K1>(pa, pb, st, soff);
                else          load_seg<K2>(pa, pb, st, soff);
                pa += BK; pb += BK;
            }
            cp_commit();         // unconditional: uniform group accounting

            const uint32_t sA = baseA + s * STAGE_SZ;
            const uint32_t sB = baseB + s * STAGE_SZ;
#pragma unroll
            for (int q = 0; q < 4; q++) {
                uint32_t a0[4], a1[4], b0[4], b1[4];
                ldm4(a0, sA + oq[q]);           // mt 0
                ldm4(a1, sA + 2048u + oq[q]);   // mt 1
                ldm4(b0, sB + oq[q]);           // j 0 (n 0..15 of warp)
                ldm4(b1, sB + 2048u + oq[q]);   // j 1 (n 16..31)
#pragma unroll
                for (int nt = 0; nt < 4; nt++) {
                    const uint32_t* bf = (nt >> 1) ? b1 : b0;
                    mma_tf32(acc[0][nt], a0, bf[nt & 1], bf[2 + (nt & 1)]);
                    mma_tf32(acc[1][nt], a1, bf[nt & 1], bf[2 + (nt & 1)]);
                }
            }
        }
    }

    // ---------------- epilogue ----------------
#pragma unroll
    for (int mt = 0; mt < 2; mt++) {
#pragma unroll
        for (int nt = 0; nt < 4; nt++) {
            const int n = tn * BN + wn * 32 + nt * 8 + tq * 2;
            const float2 bi = *(const float2*)(bias + n);
#pragma unroll
            for (int half = 0; half < 2; half++) {
                const int m = tm * BM + wm * 32 + mt * 16 + g + half * 8;
                const size_t idx = (size_t)m * NTOT + n;
                float v0 = acc[mt][nt][half * 2 + 0] + bi.x;
                float v1 = acc[mt][nt][half * 2 + 1] + bi.y;
                float2 o;
                if (MODE == 0) {
                    const float s0 = sigf(v0), s1 = sigf(v1);
                    if (!zg) {
                        const float2 h = *(const float2*)(hprev + idx);
                        o.x = tf32r(s0 * h.x);
                        o.y = tf32r(s1 * h.y);
                    } else {
                        o.x = s0;
                        o.y = s1;
                    }
                } else {
                    const float2 h = *(const float2*)(hprev + idx);
                    const float2 z = *(const float2*)(zbuf + idx);
                    o.x = z.x * tanhfast(v0) + (1.f - z.x) * h.x;
                    o.y = z.y * tanhfast(v1) + (1.f - z.y) * h.y;
                }
                *(float2*)(out + idx) = o;
            }
        }
    }
}

// ---------------- host launcher ----------------
extern "C" void kernel_launch(void* const* d_in, const int* in_sizes, int n_in,
                              void* d_out, int out_size) {
    (void)in_sizes; (void)n_in; (void)out_size;
    // metadata order: x, hprev, Wh, Wz, Wr, Uh, Uz, Ur, bh, bz, br
    const float* x     = (const float*)d_in[0];
    const float* hprev = (const float*)d_in[1];
    const float* Wh    = (const float*)d_in[2];
    const float* Wz    = (const float*)d_in[3];
    const float* Wr    = (const float*)d_in[4];
    const float* Uh    = (const float*)d_in[5];
    const float* Uz    = (const float*)d_in[6];
    const float* Ur    = (const float*)d_in[7];
    const float* bh    = (const float*)d_in[8];
    const float* bz    = (const float*)d_in[9];
    const float* br    = (const float*)d_in[10];
    float* out = (float*)d_out;

    float *px, *ph, *pWr, *pWz, *pWh, *pUr, *pUz, *pUh, *prh, *pzb;
    cudaGetSymbolAddress((void**)&px,  g_x);
    cudaGetSymbolAddress((void**)&ph,  g_h);
    cudaGetSymbolAddress((void**)&pWr, g_Wr);
    cudaGetSymbolAddress((void**)&pWz, g_Wz);
    cudaGetSymbolAddress((void**)&pWh, g_Wh);
    cudaGetSymbolAddress((void**)&pUr, g_Ur);
    cudaGetSymbolAddress((void**)&pUz, g_Uz);
    cudaGetSymbolAddress((void**)&pUh, g_Uh);
    cudaGetSymbolAddress((void**)&prh, g_rh);
    cudaGetSymbolAddress((void**)&pzb, g_zb);

    cudaFuncSetAttribute(gru_gemm<0>, cudaFuncAttributeMaxDynamicSharedMemorySize, SMEM_BYTES);
    cudaFuncSetAttribute(gru_gemm<1>, cudaFuncAttributeMaxDynamicSharedMemorySize, SMEM_BYTES);

    // tf32 pre-round all GEMM operands into scratch (one launch)
    RoundSegs S;
    S.src[0] = (const float4*)x;     S.dst[0] = (float4*)px;  S.n4[0] = MTOT * K1 / 4;
    S.src[1] = (const float4*)hprev; S.dst[1] = (float4*)ph;  S.n4[1] = MTOT * K2 / 4;
    S.src[2] = (const float4*)Wr;    S.dst[2] = (float4*)pWr; S.n4[2] = NTOT * K1 / 4;
    S.src[3] = (const float4*)Wz;    S.dst[3] = (float4*)pWz; S.n4[3] = NTOT * K1 / 4;
    S.src[4] = (const float4*)Wh;    S.dst[4] = (float4*)pWh; S.n4[4] = NTOT * K1 / 4;
    S.src[5] = (const float4*)Ur;    S.dst[5] = (float4*)pUr; S.n4[5] = NTOT * K2 / 4;
    S.src[6] = (const float4*)Uz;    S.dst[6] = (float4*)pUz; S.n4[6] = NTOT * K2 / 4;
    S.src[7] = (const float4*)Uh;    S.dst[7] = (float4*)pUh; S.n4[7] = NTOT * K2 / 4;
    round_all<<<dim3(256, 8), 256>>>(S);

    const dim3 block(256);
    // fused r+z: 2048 CTAs (N-half selects gate)
    gru_gemm<0><<<dim3(2048), block, SMEM_BYTES>>>(
        px, ph, pWr, pUr, pWz, pUz, br, bz, hprev, nullptr, prh, pzb);
    // h-gate: out = z * tanh(x@Wh^T + rh@Uh^T + bh) + (1-z) * hprev
    gru_gemm<1><<<dim3(1024), block, SMEM_BYTES>>>(
        px, prh, pWh, pUh, nullptr, nullptr, bh, nullptr, hprev, pzb, out, nullptr);
}

// round 13
// speedup vs baseline: 1.2473x; 1.0241x over previous
#include <cuda_runtime.h>
#include <cstdint>
#include <cstddef>

// ---------------- problem constants ----------------
#define MTOT 4096
#define NTOT 2048
#define K1   1024
#define K2   2048

#define BM 64
#define BN 128
#define BK 32
#define NS 2

#define KT1  (K1 / BK)           // 32
#define KTOT ((K1 + K2) / BK)    // 96

#define STAGE_A  (BM * BK * 4)               // 8192 B
#define STAGE_B  (BN * BK * 4)               // 16384 B
#define STAGE_SZ (STAGE_A + STAGE_B)         // 24576 B
#define SMEM_BYTES (NS * STAGE_SZ)           // 49152 B -> 4 CTAs/SM

// ---------------- scratch (__device__ globals: allocation-free) ----------------
__device__ float g_x [MTOT * (size_t)K1];
__device__ float g_h [MTOT * (size_t)K2];
__device__ float g_Wr[NTOT * (size_t)K1];
__device__ float g_Wz[NTOT * (size_t)K1];
__device__ float g_Wh[NTOT * (size_t)K1];
__device__ float g_Ur[NTOT * (size_t)K2];
__device__ float g_Uz[NTOT * (size_t)K2];
__device__ float g_Uh[NTOT * (size_t)K2];
__device__ float g_rh[MTOT * (size_t)NTOT];
__device__ float g_zb[MTOT * (size_t)NTOT];

// ---------------- helpers ----------------
__device__ __forceinline__ uint32_t smem_u32(const void* p) {
    uint32_t a;
    asm("{ .reg .u64 t; cvta.to.shared.u64 t, %1; cvt.u32.u64 %0, t; }" : "=r"(a) : "l"(p));
    return a;
}

__device__ __forceinline__ void cp16(uint32_t dst, const void* src) {
    asm volatile("cp.async.cg.shared.global [%0], [%1], 16;" :: "r"(dst), "l"(src));
}
__device__ __forceinline__ void cp_commit() {
    asm volatile("cp.async.commit_group;" ::: "memory");
}
__device__ __forceinline__ void cp_wait1() {
    asm volatile("cp.async.wait_group 1;" ::: "memory");
}

// ldmatrix x4 (b16): four 8x8 b16 matrices == four 8row x 4col fp32 tiles.
__device__ __forceinline__ void ldm4(uint32_t* r, uint32_t addr) {
    asm volatile("ldmatrix.sync.aligned.m8n8.x4.shared.b16 {%0,%1,%2,%3}, [%4];"
                 : "=r"(r[0]), "=r"(r[1]), "=r"(r[2]), "=r"(r[3]) : "r"(addr));
}

__device__ __forceinline__ void mma_tf32(float* c, const uint32_t* a, uint32_t b0, uint32_t b1) {
    asm volatile(
        "mma.sync.aligned.m16n8k8.row.col.f32.tf32.tf32.f32 "
        "{%0,%1,%2,%3}, {%4,%5,%6,%7}, {%8,%9}, {%0,%1,%2,%3};"
        : "+f"(c[0]), "+f"(c[1]), "+f"(c[2]), "+f"(c[3])
        : "r"(a[0]), "r"(a[1]), "r"(a[2]), "r"(a[3]), "r"(b0), "r"(b1));
}

__device__ __forceinline__ float tf32r(float x) {
    float r;
    asm("cvt.rna.tf32.f32 %0, %1;" : "=f"(r) : "f"(x));
    return r;
}
__device__ __forceinline__ float sigf(float v) { return 1.f / (1.f + __expf(-v)); }
__device__ __forceinline__ float tanhfast(float v) { return 2.f / (1.f + __expf(-2.f * v)) - 1.f; }

// ---------------- tf32 rounding pre-pass (one launch, 8 segments) ----------------
struct RoundSegs {
    const float4* src[8];
    float4*       dst[8];
    int           n4[8];
};

__global__ void round_all(RoundSegs S) {
    const int s = blockIdx.y;
    const float4* __restrict__ in = S.src[s];
    float4* __restrict__ out = S.dst[s];
    const int n4 = S.n4[s];
    for (int i = blockIdx.x * blockDim.x + threadIdx.x; i < n4; i += gridDim.x * blockDim.x) {
        float4 v = in[i];
        v.x = tf32r(v.x); v.y = tf32r(v.y); v.z = tf32r(v.z); v.w = tf32r(v.w);
        out[i] = v;
    }
}

// ---------------- tile loader (compile-time leading dimension) ----------------
template <int LD>
__device__ __forceinline__ void load_seg(const float* __restrict__ pa,
                                         const float* __restrict__ pb,
                                         uint32_t st, uint32_t soff) {
#pragma unroll
    for (int i = 0; i < 2; i++)
        cp16(st + soff + i * 4096u, pa + (size_t)i * 32 * LD);
#pragma unroll
    for (int i = 0; i < 4; i++)
        cp16(st + STAGE_A + soff + i * 4096u, pb + (size_t)i * 32 * LD);
}

// ---------------- fused dual-source GEMM ----------------
// MODE 0 (fused r+z): grid 2048; N-half selects gate:
//   r: outr = tf32(sigmoid(acc+br) * hprev)   z: outz = sigmoid(acc+bz)
// MODE 1 (h): grid 1024; out = z*tanh(acc+bh) + (1-z)*hprev
template <int MODE>
__global__ void __launch_bounds__(256, 4) gru_gemm(
    const float* __restrict__ A1, const float* __restrict__ A2,
    const float* __restrict__ B1r, const float* __restrict__ B2r,
    const float* __restrict__ B1z, const float* __restrict__ B2z,
    const float* __restrict__ biasr, const float* __restrict__ biasz,
    const float* __restrict__ hprev, const float* __restrict__ zbuf,
    float* __restrict__ outr, float* __restrict__ outz)
{
    extern __shared__ char smem[];
    const uint32_t sbase = smem_u32(smem);
    const int tid = threadIdx.x;
    const int wid = tid >> 5;
    const int lid = tid & 31;
    const int wm  = wid >> 2;     // 0..1 (M)
    const int wn  = wid & 3;      // 0..3 (N)
    const int bx  = blockIdx.x;
    const int tm  = bx & 63;      // fast dim -> B-tile sharing in L2

    int tn;
    bool zg = false;
    const float* B1;
    if (MODE == 0) {
        const int tnn = bx >> 6;              // 0..31
        zg = tnn >= 16;
        tn = tnn & 15;
        B1 = zg ? B1z : B1r;
    } else {
        tn = bx >> 6;                         // 0..15
        B1 = B1r;
    }

    // -------- loader per-thread constants --------
    const int tr = tid >> 3;                 // 0..31
    const int c  = tid & 7;                  // 16B chunk
    const uint32_t soff = (uint32_t)tr * 128u + (uint32_t)((c ^ (tr & 7)) << 4);

    const float* pa = A1 + (size_t)(tm * BM + tr) * K1 + c * 4;
    const float* pb = B1 + (size_t)(tn * BN + tr) * K1 + c * 4;

    // -------- ldmatrix addressing (lean) --------
    const int lr = lid & 7;
    const int mi = lid >> 3;
    const int lo = mi & 1;        // +8 rows
    const int hi = mi >> 1;       // +1 chunk (k+4)

    const uint32_t baseA = sbase + (uint32_t)(wm * 4096 + lo * 1024 + lr * 128);
    const uint32_t baseB = sbase + STAGE_A + (uint32_t)(wn * 4096 + lo * 1024 + lr * 128);

    float acc[2][4][4];
#pragma unroll
    for (int mt = 0; mt < 2; mt++)
#pragma unroll
        for (int nt = 0; nt < 4; nt++)
#pragma unroll
            for (int i = 0; i < 4; i++) acc[mt][nt][i] = 0.f;

    // -------- prologue: tile 0 into stage 0 --------
    load_seg<K1>(pa, pb, sbase, soff);
    pa += BK; pb += BK;
    cp_commit();

    // -------- mainloop (NS=2): 2 syncs per tile --------
#pragma unroll 1
    for (int kt0 = 0; kt0 < KTOT; kt0 += 2) {
#pragma unroll
        for (int s = 0; s < 2; s++) {
            const int kt = kt0 + s;
            // (entry: all warps finished computing tile kt-1 -> stage 1-s is free)
            const int lt = kt + 1;
            if (lt < KTOT) {
                if (lt == KT1) {   // switch to second K-source
                    pa = A2 + (size_t)(tm * BM + tr) * K2 + c * 4;
                    pb = (MODE == 0 ? (zg ? B2z : B2r) : B2r)
                         + (size_t)(tn * BN + tr) * K2 + c * 4;
                }
                const uint32_t st = sbase + (1 - s) * STAGE_SZ;
                if (lt < KT1) load_seg<K1>(pa, pb, st, soff);
                else          load_seg<K2>(pa, pb, st, soff);
                pa += BK; pb += BK;
            }
            cp_commit();         // uniform group accounting
            cp_wait1();          // own copies of tile kt complete
            __syncthreads();     // all threads' copies of tile kt visible

            const uint32_t sA = baseA + s * STAGE_SZ;
            const uint32_t sB = baseB + s * STAGE_SZ;
#pragma unroll
            for (int q = 0; q < 4; q++) {
                const uint32_t oq = (uint32_t)((((2 * q + hi) ^ lr)) << 4);
                uint32_t a0[4], a1[4], b[4];
                ldm4(a0, sA + oq);           // mt 0
                ldm4(a1, sA + 2048u + oq);   // mt 1
                ldm4(b, sB + oq);            // n 0..15 of warp slice
                mma_tf32(acc[0][0], a0, b[0], b[2]);
                mma_tf32(acc[1][0], a1, b[0], b[2]);
                mma_tf32(acc[0][1], a0, b[1], b[3]);
                mma_tf32(acc[1][1], a1, b[1], b[3]);
                ldm4(b, sB + 2048u + oq);    // n 16..31
                mma_tf32(acc[0][2], a0, b[0], b[2]);
                mma_tf32(acc[1][2], a1, b[0], b[2]);
                mma_tf32(acc[0][3], a0, b[1], b[3]);
                mma_tf32(acc[1][3], a1, b[1], b[3]);
            }
            __syncthreads();     // computing done -> stage s may be reloaded
        }
    }

    // ---------------- epilogue ----------------
    const int g  = lid >> 2;
    const int tq = lid & 3;
    const float* bias = (MODE == 0) ? (zg ? biasz : biasr) : biasr;
    float* out        = (MODE == 0) ? (zg ? outz : outr) : outr;

#pragma unroll
    for (int mt = 0; mt < 2; mt++) {
#pragma unroll
        for (int nt = 0; nt < 4; nt++) {
            const int n = tn * BN + wn * 32 + nt * 8 + tq * 2;
            const float2 bi = *(const float2*)(bias + n);
#pragma unroll
            for (int half = 0; half < 2; half++) {
                const int m = tm * BM + wm * 32 + mt * 16 + g + half * 8;
                const size_t idx = (size_t)m * NTOT + n;
                float v0 = acc[mt][nt][half * 2 + 0] + bi.x;
                float v1 = acc[mt][nt][half * 2 + 1] + bi.y;
                float2 o;
                if (MODE == 0) {
                    const float s0 = sigf(v0), s1 = sigf(v1);
                    if (!zg) {
                        const float2 h = *(const float2*)(hprev + idx);
                        o.x = tf32r(s0 * h.x);
                        o.y = tf32r(s1 * h.y);
                    } else {
                        o.x = s0;
                        o.y = s1;
                    }
                } else {
                    const float2 h = *(const float2*)(hprev + idx);
                    const float2 z = *(const float2*)(zbuf + idx);
                    o.x = z.x * tanhfast(v0) + (1.f - z.x) * h.x;
                    o.y = z.y * tanhfast(v1) + (1.f - z.y) * h.y;
                }
                *(float2*)(out + idx) = o;
            }
        }
    }
}

// ---------------- host launcher ----------------
extern "C" void kernel_launch(void* const* d_in, const int* in_sizes, int n_in,
                              void* d_out, int out_size) {
    (void)in_sizes; (void)n_in; (void)out_size;
    // metadata order: x, hprev, Wh, Wz, Wr, Uh, Uz, Ur, bh, bz, br
    const float* x     = (const float*)d_in[0];
    const float* hprev = (const float*)d_in[1];
    const float* Wh    = (const float*)d_in[2];
    const float* Wz    = (const float*)d_in[3];
    const float* Wr    = (const float*)d_in[4];
    const float* Uh    = (const float*)d_in[5];
    const float* Uz    = (const float*)d_in[6];
    const float* Ur    = (const float*)d_in[7];
    const float* bh    = (const float*)d_in[8];
    const float* bz    = (const float*)d_in[9];
    const float* br    = (const float*)d_in[10];
    float* out = (float*)d_out;

    float *px, *ph, *pWr, *pWz, *pWh, *pUr, *pUz, *pUh, *prh, *pzb;
    cudaGetSymbolAddress((void**)&px,  g_x);
    cudaGetSymbolAddress((void**)&ph,  g_h);
    cudaGetSymbolAddress((void**)&pWr, g_Wr);
    cudaGetSymbolAddress((void**)&pWz, g_Wz);
    cudaGetSymbolAddress((void**)&pWh, g_Wh);
    cudaGetSymbolAddress((void**)&pUr, g_Ur);
    cudaGetSymbolAddress((void**)&pUz, g_Uz);
    cudaGetSymbolAddress((void**)&pUh, g_Uh);
    cudaGetSymbolAddress((void**)&prh, g_rh);
    cudaGetSymbolAddress((void**)&pzb, g_zb);

    cudaFuncSetAttribute(gru_gemm<0>, cudaFuncAttributeMaxDynamicSharedMemorySize, SMEM_BYTES);
    cudaFuncSetAttribute(gru_gemm<1>, cudaFuncAttributeMaxDynamicSharedMemorySize, SMEM_BYTES);

    // tf32 pre-round all GEMM operands into scratch (one launch)
    RoundSegs S;
    S.src[0] = (const float4*)x;     S.dst[0] = (float4*)px;  S.n4[0] = MTOT * K1 / 4;
    S.src[1] = (const float4*)hprev; S.dst[1] = (float4*)ph;  S.n4[1] = MTOT * K2 / 4;
    S.src[2] = (const float4*)Wr;    S.dst[2] = (float4*)pWr; S.n4[2] = NTOT * K1 / 4;
    S.src[3] = (const float4*)Wz;    S.dst[3] = (float4*)pWz; S.n4[3] = NTOT * K1 / 4;
    S.src[4] = (const float4*)Wh;    S.dst[4] = (float4*)pWh; S.n4[4] = NTOT * K1 / 4;
    S.src[5] = (const float4*)Ur;    S.dst[5] = (float4*)pUr; S.n4[5] = NTOT * K2 / 4;
    S.src[6] = (const float4*)Uz;    S.dst[6] = (float4*)pUz; S.n4[6] = NTOT * K2 / 4;
    S.src[7] = (const float4*)Uh;    S.dst[7] = (float4*)pUh; S.n4[7] = NTOT * K2 / 4;
    round_all<<<dim3(256, 8), 256>>>(S);

    const dim3 block(256);
    // fused r+z: 2048 CTAs (N-half selects gate)
    gru_gemm<0><<<dim3(2048), block, SMEM_BYTES>>>(
        px, ph, pWr, pUr, pWz, pUz, br, bz, hprev, nullptr, prh, pzb);
    // h-gate: out = z * tanh(x@Wh^T + rh@Uh^T + bh) + (1-z) * hprev
    gru_gemm<1><<<dim3(1024), block, SMEM_BYTES>>>(
        px, prh, pWh, pUh, nullptr, nullptr, bh, nullptr, hprev, pzb, out, nullptr);
}

// round 14
// speedup vs baseline: 1.3282x; 1.0649x over previous
#include <cuda_runtime.h>
#include <cstdint>
#include <cstddef>

// ---------------- problem constants ----------------
#define MTOT 4096
#define NTOT 2048
#define K1   1024
#define K2   2048

#define BM 64
#define BN 128
#define BK 32
#define NS 2
#define NTHREADS 128

#define KT1  (K1 / BK)           // 32
#define KTOT ((K1 + K2) / BK)    // 96

#define STAGE_A  (BM * BK * 4)               // 8192 B
#define STAGE_B  (BN * BK * 4)               // 16384 B
#define STAGE_SZ (STAGE_A + STAGE_B)         // 24576 B
#define SMEM_BYTES (NS * STAGE_SZ)           // 49152 B -> 4 CTAs/SM, 512 thr/SM

// ---------------- scratch (__device__ globals: allocation-free) ----------------
__device__ float g_x [MTOT * (size_t)K1];
__device__ float g_h [MTOT * (size_t)K2];
__device__ float g_Wr[NTOT * (size_t)K1];
__device__ float g_Wz[NTOT * (size_t)K1];
__device__ float g_Wh[NTOT * (size_t)K1];
__device__ float g_Ur[NTOT * (size_t)K2];
__device__ float g_Uz[NTOT * (size_t)K2];
__device__ float g_Uh[NTOT * (size_t)K2];
__device__ float g_rh[MTOT * (size_t)NTOT];
__device__ float g_zb[MTOT * (size_t)NTOT];

// ---------------- helpers ----------------
__device__ __forceinline__ uint32_t smem_u32(const void* p) {
    uint32_t a;
    asm("{ .reg .u64 t; cvta.to.shared.u64 t, %1; cvt.u32.u64 %0, t; }" : "=r"(a) : "l"(p));
    return a;
}

__device__ __forceinline__ void cp16(uint32_t dst, const void* src) {
    asm volatile("cp.async.cg.shared.global [%0], [%1], 16;" :: "r"(dst), "l"(src));
}
__device__ __forceinline__ void cp_commit() {
    asm volatile("cp.async.commit_group;" ::: "memory");
}
__device__ __forceinline__ void cp_wait1() {
    asm volatile("cp.async.wait_group 1;" ::: "memory");
}

// ldmatrix x4 (b16): four 8x8 b16 matrices == four 8row x 4col fp32 tiles.
__device__ __forceinline__ void ldm4(uint32_t* r, uint32_t addr) {
    asm volatile("ldmatrix.sync.aligned.m8n8.x4.shared.b16 {%0,%1,%2,%3}, [%4];"
                 : "=r"(r[0]), "=r"(r[1]), "=r"(r[2]), "=r"(r[3]) : "r"(addr));
}

__device__ __forceinline__ void mma_tf32(float* c, const uint32_t* a, uint32_t b0, uint32_t b1) {
    asm volatile(
        "mma.sync.aligned.m16n8k8.row.col.f32.tf32.tf32.f32 "
        "{%0,%1,%2,%3}, {%4,%5,%6,%7}, {%8,%9}, {%0,%1,%2,%3};"
        : "+f"(c[0]), "+f"(c[1]), "+f"(c[2]), "+f"(c[3])
        : "r"(a[0]), "r"(a[1]), "r"(a[2]), "r"(a[3]), "r"(b0), "r"(b1));
}

__device__ __forceinline__ float tf32r(float x) {
    float r;
    asm("cvt.rna.tf32.f32 %0, %1;" : "=f"(r) : "f"(x));
    return r;
}
__device__ __forceinline__ float sigf(float v) { return 1.f / (1.f + __expf(-v)); }
__device__ __forceinline__ float tanhfast(float v) { return 2.f / (1.f + __expf(-2.f * v)) - 1.f; }

// ---------------- tf32 rounding pre-pass (one launch, 8 segments) ----------------
struct RoundSegs {
    const float4* src[8];
    float4*       dst[8];
    int           n4[8];
};

__global__ void round_all(RoundSegs S) {
    const int s = blockIdx.y;
    const float4* __restrict__ in = S.src[s];
    float4* __restrict__ out = S.dst[s];
    const int n4 = S.n4[s];
    for (int i = blockIdx.x * blockDim.x + threadIdx.x; i < n4; i += gridDim.x * blockDim.x) {
        float4 v = in[i];
        v.x = tf32r(v.x); v.y = tf32r(v.y); v.z = tf32r(v.z); v.w = tf32r(v.w);
        out[i] = v;
    }
}

// ---------------- tile loader (compile-time leading dimension) ----------------
// 128 threads: tr = tid>>3 (0..15), c = tid&7. A: 4 row-groups, B: 8 row-groups.
template <int LD>
__device__ __forceinline__ void load_seg(const float* __restrict__ pa,
                                         const float* __restrict__ pb,
                                         uint32_t st, uint32_t soff) {
#pragma unroll
    for (int i = 0; i < 4; i++)
        cp16(st + soff + i * 2048u, pa + (size_t)i * 16 * LD);
#pragma unroll
    for (int i = 0; i < 8; i++)
        cp16(st + STAGE_A + soff + i * 2048u, pb + (size_t)i * 16 * LD);
}

// ---------------- fused dual-source GEMM ----------------
// MODE 0 (fused r+z): grid 2048; N-half selects gate:
//   r: outr = tf32(sigmoid(acc+br) * hprev)   z: outz = sigmoid(acc+bz)
// MODE 1 (h): grid 1024; out = z*tanh(acc+bh) + (1-z)*hprev
template <int MODE>
__global__ void __launch_bounds__(NTHREADS, 4) gru_gemm(
    const float* __restrict__ A1, const float* __restrict__ A2,
    const float* __restrict__ B1r, const float* __restrict__ B2r,
    const float* __restrict__ B1z, const float* __restrict__ B2z,
    const float* __restrict__ biasr, const float* __restrict__ biasz,
    const float* __restrict__ hprev, const float* __restrict__ zbuf,
    float* __restrict__ outr, float* __restrict__ outz)
{
    extern __shared__ char smem[];
    const uint32_t sbase = smem_u32(smem);
    const int tid = threadIdx.x;
    const int wid = tid >> 5;
    const int lid = tid & 31;
    const int wm  = wid >> 1;     // 0..1 (M), 32 rows each
    const int wn  = wid & 1;      // 0..1 (N), 64 cols each
    const int bx  = blockIdx.x;
    const int tm  = bx & 63;      // fast dim -> B-tile sharing in L2

    int tn;
    bool zg = false;
    const float* B1;
    if (MODE == 0) {
        const int tnn = bx >> 6;              // 0..31
        zg = tnn >= 16;
        tn = tnn & 15;
        B1 = zg ? B1z : B1r;
    } else {
        tn = bx >> 6;                         // 0..15
        B1 = B1r;
    }

    // -------- loader per-thread constants --------
    const int tr = tid >> 3;                 // 0..15
    const int c  = tid & 7;                  // 16B chunk
    const uint32_t soff = (uint32_t)tr * 128u + (uint32_t)((c ^ (tr & 7)) << 4);

    const float* pa = A1 + (size_t)(tm * BM + tr) * K1 + c * 4;
    const float* pb = B1 + (size_t)(tn * BN + tr) * K1 + c * 4;

    // -------- ldmatrix addressing (lean) --------
    const int lr = lid & 7;
    const int mi = lid >> 3;
    const int lo = mi & 1;        // +8 rows
    const int hi = mi >> 1;       // +1 chunk (k+4)

    const uint32_t baseA = sbase + (uint32_t)(wm * 4096 + lo * 1024 + lr * 128);
    const uint32_t baseB = sbase + STAGE_A + (uint32_t)(wn * 8192 + lo * 1024 + lr * 128);

    float acc[2][8][4];
#pragma unroll
    for (int mt = 0; mt < 2; mt++)
#pragma unroll
        for (int nt = 0; nt < 8; nt++)
#pragma unroll
            for (int i = 0; i < 4; i++) acc[mt][nt][i] = 0.f;

    // -------- prologue: tile 0 into stage 0 --------
    load_seg<K1>(pa, pb, sbase, soff);
    pa += BK; pb += BK;
    cp_commit();

    // -------- mainloop (NS=2): 2 syncs per tile --------
#pragma unroll 1
    for (int kt0 = 0; kt0 < KTOT; kt0 += 2) {
#pragma unroll
        for (int s = 0; s < 2; s++) {
            const int kt = kt0 + s;
            const int lt = kt + 1;
            if (lt < KTOT) {
                if (lt == KT1) {   // switch to second K-source
                    pa = A2 + (size_t)(tm * BM + tr) * K2 + c * 4;
                    pb = (MODE == 0 ? (zg ? B2z : B2r) : B2r)
                         + (size_t)(tn * BN + tr) * K2 + c * 4;
                }
                const uint32_t st = sbase + (1 - s) * STAGE_SZ;
                if (lt < KT1) load_seg<K1>(pa, pb, st, soff);
                else          load_seg<K2>(pa, pb, st, soff);
                pa += BK; pb += BK;
            }
            cp_commit();         // uniform group accounting
            cp_wait1();          // own copies of tile kt complete
            __syncthreads();     // all 4 warps' copies of tile kt visible

            const uint32_t sA = baseA + s * STAGE_SZ;
            const uint32_t sB = baseB + s * STAGE_SZ;
#pragma unroll
            for (int q = 0; q < 4; q++) {
                const uint32_t oq = (uint32_t)((((2 * q + hi) ^ lr)) << 4);
                uint32_t a0[4], a1[4], b[4];
                ldm4(a0, sA + oq);           // m rows 0..15 of warp tile
                ldm4(a1, sA + 2048u + oq);   // m rows 16..31
#pragma unroll
                for (int j = 0; j < 4; j++) {
                    ldm4(b, sB + (uint32_t)(j * 2048) + oq);   // n 16-col group j
                    mma_tf32(acc[0][2 * j + 0], a0, b[0], b[2]);
                    mma_tf32(acc[1][2 * j + 0], a1, b[0], b[2]);
                    mma_tf32(acc[0][2 * j + 1], a0, b[1], b[3]);
                    mma_tf32(acc[1][2 * j + 1], a1, b[1], b[3]);
                }
            }
            __syncthreads();     // computing done -> stage s may be reloaded
        }
    }

    // ---------------- epilogue ----------------
    const int g  = lid >> 2;
    const int tq = lid & 3;
    const float* bias = (MODE == 0) ? (zg ? biasz : biasr) : biasr;
    float* out        = (MODE == 0) ? (zg ? outz : outr) : outr;

#pragma unroll
    for (int mt = 0; mt < 2; mt++) {
#pragma unroll
        for (int nt = 0; nt < 8; nt++) {
            const int n = tn * BN + wn * 64 + nt * 8 + tq * 2;
            const float2 bi = *(const float2*)(bias + n);
#pragma unroll
            for (int half = 0; half < 2; half++) {
                const int m = tm * BM + wm * 32 + mt * 16 + g + half * 8;
                const size_t idx = (size_t)m * NTOT + n;
                float v0 = acc[mt][nt][half * 2 + 0] + bi.x;
                float v1 = acc[mt][nt][half * 2 + 1] + bi.y;
                float2 o;
                if (MODE == 0) {
                    const float s0 = sigf(v0), s1 = sigf(v1);
                    if (!zg) {
                        const float2 h = *(const float2*)(hprev + idx);
                        o.x = tf32r(s0 * h.x);
                        o.y = tf32r(s1 * h.y);
                    } else {
                        o.x = s0;
                        o.y = s1;
                    }
                } else {
                    const float2 h = *(const float2*)(hprev + idx);
                    const float2 z = *(const float2*)(zbuf + idx);
                    o.x = z.x * tanhfast(v0) + (1.f - z.x) * h.x;
                    o.y = z.y * tanhfast(v1) + (1.f - z.y) * h.y;
                }
                *(float2*)(out + idx) = o;
            }
        }
    }
}

// ---------------- host launcher ----------------
extern "C" void kernel_launch(void* const* d_in, const int* in_sizes, int n_in,
                              void* d_out, int out_size) {
    (void)in_sizes; (void)n_in; (void)out_size;
    // metadata order: x, hprev, Wh, Wz, Wr, Uh, Uz, Ur, bh, bz, br
    const float* x     = (const float*)d_in[0];
    const float* hprev = (const float*)d_in[1];
    const float* Wh    = (const float*)d_in[2];
    const float* Wz    = (const float*)d_in[3];
    const float* Wr    = (const float*)d_in[4];
    const float* Uh    = (const float*)d_in[5];
    const float* Uz    = (const float*)d_in[6];
    const float* Ur    = (const float*)d_in[7];
    const float* bh    = (const float*)d_in[8];
    const float* bz    = (const float*)d_in[9];
    const float* br    = (const float*)d_in[10];
    float* out = (float*)d_out;

    float *px, *ph, *pWr, *pWz, *pWh, *pUr, *pUz, *pUh, *prh, *pzb;
    cudaGetSymbolAddress((void**)&px,  g_x);
    cudaGetSymbolAddress((void**)&ph,  g_h);
    cudaGetSymbolAddress((void**)&pWr, g_Wr);
    cudaGetSymbolAddress((void**)&pWz, g_Wz);
    cudaGetSymbolAddress((void**)&pWh, g_Wh);
    cudaGetSymbolAddress((void**)&pUr, g_Ur);
    cudaGetSymbolAddress((void**)&pUz, g_Uz);
    cudaGetSymbolAddress((void**)&pUh, g_Uh);
    cudaGetSymbolAddress((void**)&prh, g_rh);
    cudaGetSymbolAddress((void**)&pzb, g_zb);

    cudaFuncSetAttribute(gru_gemm<0>, cudaFuncAttributeMaxDynamicSharedMemorySize, SMEM_BYTES);
    cudaFuncSetAttribute(gru_gemm<1>, cudaFuncAttributeMaxDynamicSharedMemorySize, SMEM_BYTES);

    // tf32 pre-round all GEMM operands into scratch (one launch)
    RoundSegs S;
    S.src[0] = (const float4*)x;     S.dst[0] = (float4*)px;  S.n4[0] = MTOT * K1 / 4;
    S.src[1] = (const float4*)hprev; S.dst[1] = (float4*)ph;  S.n4[1] = MTOT * K2 / 4;
    S.src[2] = (const float4*)Wr;    S.dst[2] = (float4*)pWr; S.n4[2] = NTOT * K1 / 4;
    S.src[3] = (const float4*)Wz;    S.dst[3] = (float4*)pWz; S.n4[3] = NTOT * K1 / 4;
    S.src[4] = (const float4*)Wh;    S.dst[4] = (float4*)pWh; S.n4[4] = NTOT * K1 / 4;
    S.src[5] = (const float4*)Ur;    S.dst[5] = (float4*)pUr; S.n4[5] = NTOT * K2 / 4;
    S.src[6] = (const float4*)Uz;    S.dst[6] = (float4*)pUz; S.n4[6] = NTOT * K2 / 4;
    S.src[7] = (const float4*)Uh;    S.dst[7] = (float4*)pUh; S.n4[7] = NTOT * K2 / 4;
    round_all<<<dim3(256, 8), 256>>>(S);

    const dim3 block(NTHREADS);
    // fused r+z: 2048 CTAs (N-half selects gate)
    gru_gemm<0><<<dim3(2048), block, SMEM_BYTES>>>(
        px, ph, pWr, pUr, pWz, pUz, br, bz, hprev, nullptr, prh, pzb);
    // h-gate: out = z * tanh(x@Wh^T + rh@Uh^T + bh) + (1-z) * hprev
    gru_gemm<1><<<dim3(1024), block, SMEM_BYTES>>>(
        px, prh, pWh, pUh, nullptr, nullptr, bh, nullptr, hprev, pzb, out, nullptr);
}